// round 2
// baseline (speedup 1.0000x reference)
#include <cuda_runtime.h>
#include <math.h>

// Problem constants
#define BATCH  16384
#define DMODEL 512
#define NHEAD  4
#define KDIM   128
#define ROWS3  (BATCH*3)

// ---------------------------------------------------------------------------
// Scratch (static __device__ arrays — the sanctioned no-alloc workaround)
// ---------------------------------------------------------------------------
__device__ float g_x  [ROWS3*DMODEL];   // [B,3,D]: fp,rp,mp  (also concat view [B,1536])
__device__ float g_h  [BATCH*256];      // MLP hidden
__device__ float g_aw [BATCH*3];        // adaptive softmax weights
__device__ float g_q  [ROWS3*DMODEL];
__device__ float g_k  [ROWS3*DMODEL];
__device__ float g_v  [ROWS3*DMODEL];
__device__ float g_ctx[ROWS3*DMODEL];
__device__ float g_o  [ROWS3*DMODEL];
__device__ float g_y  [ROWS3*DMODEL];   // LN1 output
__device__ float g_wt [BATCH*DMODEL];   // weighted combination
__device__ float g_gt [BATCH*DMODEL];   // sigmoid gate

// ---------------------------------------------------------------------------
// tf32 GEMM:  C[M,N] = act(A[M,K] @ W[K,N] + bias[N])
// CTA tile 128x64x32, 256 threads (8 warps as 4x2), warp tile 32x32,
// mma.sync.m16n8k8 tf32, fp32 accumulate. M%128==0, N%64==0, K%32==0 assumed.
// ---------------------------------------------------------------------------
__device__ __forceinline__ unsigned f2tf(float x) {
    unsigned u;
    asm("cvt.rna.tf32.f32 %0, %1;" : "=r"(u) : "f"(x));
    return u;
}

#define MMA_TF32(d, a, b)                                                      \
    asm volatile(                                                              \
        "mma.sync.aligned.m16n8k8.row.col.f32.tf32.tf32.f32 "                  \
        "{%0,%1,%2,%3}, {%4,%5,%6,%7}, {%8,%9}, {%0,%1,%2,%3};"                \
        : "+f"(d[0]), "+f"(d[1]), "+f"(d[2]), "+f"(d[3])                       \
        : "r"(a[0]), "r"(a[1]), "r"(a[2]), "r"(a[3]), "r"(b[0]), "r"(b[1]))

__device__ __forceinline__ void ldg_tiles(const float* __restrict__ Ab,
                                          const float* __restrict__ Wb,
                                          int lda, int ldw, int kb, int tid,
                                          float4 (&pa)[4], float4 (&pb)[2]) {
#pragma unroll
    for (int i = 0; i < 4; i++) {
        int c = tid + (i << 8);                 // 0..1023 tiles of A (128x8 float4)
        pa[i] = *reinterpret_cast<const float4*>(Ab + (c >> 3) * lda + kb + ((c & 7) << 2));
    }
#pragma unroll
    for (int i = 0; i < 2; i++) {
        int c = tid + (i << 8);                 // 0..511 tiles of B (32x16 float4)
        pb[i] = *reinterpret_cast<const float4*>(Wb + (kb + (c >> 4)) * ldw + ((c & 15) << 2));
    }
}

__device__ __forceinline__ void sts_tiles(float (*As)[36], float (*Bs)[72], int tid,
                                          const float4 (&pa)[4], const float4 (&pb)[2]) {
#pragma unroll
    for (int i = 0; i < 4; i++) {
        int c = tid + (i << 8);
        float4 s = pa[i], cv;
        cv.x = __uint_as_float(f2tf(s.x));
        cv.y = __uint_as_float(f2tf(s.y));
        cv.z = __uint_as_float(f2tf(s.z));
        cv.w = __uint_as_float(f2tf(s.w));
        *reinterpret_cast<float4*>(&As[c >> 3][(c & 7) << 2]) = cv;
    }
#pragma unroll
    for (int i = 0; i < 2; i++) {
        int c = tid + (i << 8);
        float4 s = pb[i], cv;
        cv.x = __uint_as_float(f2tf(s.x));
        cv.y = __uint_as_float(f2tf(s.y));
        cv.z = __uint_as_float(f2tf(s.z));
        cv.w = __uint_as_float(f2tf(s.w));
        *reinterpret_cast<float4*>(&Bs[c >> 4][(c & 15) << 2]) = cv;
    }
}

// ACT: 0 = none, 1 = relu, 2 = sigmoid
template <int ACT>
__global__ void __launch_bounds__(256) gemm_tf32(
    const float* __restrict__ A, int lda,
    const float* __restrict__ W, int ldw,
    const float* __restrict__ bias,
    float* __restrict__ C, int ldc, int K)
{
    __shared__ float As[128][36];   // [m][k], stride 36 -> conflict-free A frags
    __shared__ float Bs[32][72];    // [k][n], stride 72 -> conflict-free B frags

    const int tid  = threadIdx.x;
    const int lane = tid & 31;
    const int warp = tid >> 5;
    const int wr = warp >> 1;       // warp row 0..3 (32 rows each)
    const int wc = warp & 1;        // warp col 0..1 (32 cols each)
    const int g = lane >> 2;        // groupID
    const int t = lane & 3;         // thread-in-group
    const int m0 = blockIdx.y * 128;
    const int n0 = blockIdx.x * 64;

    const float* Ab = A + m0 * lda;
    const float* Wb = W + n0;

    float acc[2][4][4];
#pragma unroll
    for (int i = 0; i < 2; i++)
#pragma unroll
        for (int j = 0; j < 4; j++)
#pragma unroll
            for (int r = 0; r < 4; r++) acc[i][j][r] = 0.f;

    float4 pa[4], pb[2];
    ldg_tiles(Ab, Wb, lda, ldw, 0, tid, pa, pb);
    sts_tiles(As, Bs, tid, pa, pb);
    __syncthreads();

    for (int kb = 32;; kb += 32) {
        const bool more = (kb < K);
        if (more) ldg_tiles(Ab, Wb, lda, ldw, kb, tid, pa, pb);

#pragma unroll
        for (int kk = 0; kk < 4; kk++) {
            const int k8 = kk * 8;
            unsigned a[2][4], b[4][2];
#pragma unroll
            for (int mi = 0; mi < 2; mi++) {
                const int mr = wr * 32 + mi * 16 + g;
                a[mi][0] = __float_as_uint(As[mr    ][k8 + t    ]);
                a[mi][1] = __float_as_uint(As[mr + 8][k8 + t    ]);
                a[mi][2] = __float_as_uint(As[mr    ][k8 + t + 4]);
                a[mi][3] = __float_as_uint(As[mr + 8][k8 + t + 4]);
            }
#pragma unroll
            for (int ni = 0; ni < 4; ni++) {
                const int nc = wc * 32 + ni * 8 + g;
                b[ni][0] = __float_as_uint(Bs[k8 + t    ][nc]);
                b[ni][1] = __float_as_uint(Bs[k8 + t + 4][nc]);
            }
#pragma unroll
            for (int mi = 0; mi < 2; mi++)
#pragma unroll
                for (int ni = 0; ni < 4; ni++) MMA_TF32(acc[mi][ni], a[mi], b[ni]);
        }
        __syncthreads();
        if (!more) break;
        sts_tiles(As, Bs, tid, pa, pb);
        __syncthreads();
    }

    // epilogue: bias + activation, float2 stores
#pragma unroll
    for (int mi = 0; mi < 2; mi++) {
#pragma unroll
        for (int ni = 0; ni < 4; ni++) {
            const int row = m0 + wr * 32 + mi * 16 + g;
            const int col = n0 + wc * 32 + ni * 8 + 2 * t;
            const float b0 = bias[col], b1 = bias[col + 1];
            float v0 = acc[mi][ni][0] + b0;
            float v1 = acc[mi][ni][1] + b1;
            float v2 = acc[mi][ni][2] + b0;
            float v3 = acc[mi][ni][3] + b1;
            if (ACT == 1) {
                v0 = fmaxf(v0, 0.f); v1 = fmaxf(v1, 0.f);
                v2 = fmaxf(v2, 0.f); v3 = fmaxf(v3, 0.f);
            } else if (ACT == 2) {
                v0 = 1.f / (1.f + expf(-v0)); v1 = 1.f / (1.f + expf(-v1));
                v2 = 1.f / (1.f + expf(-v2)); v3 = 1.f / (1.f + expf(-v3));
            }
            *reinterpret_cast<float2*>(&C[row * ldc + col])       = make_float2(v0, v1);
            *reinterpret_cast<float2*>(&C[(row + 8) * ldc + col]) = make_float2(v2, v3);
        }
    }
}

// ---------------------------------------------------------------------------
// Adaptive weights: aw[b,:] = softmax(h[b,:] @ Wa2 + ba2).  One warp per row.
// ---------------------------------------------------------------------------
__global__ void __launch_bounds__(256) aw_kernel(
    const float* __restrict__ h, const float* __restrict__ Wa2,
    const float* __restrict__ ba2, float* __restrict__ aw)
{
    __shared__ float w2[768];
    const int tid = threadIdx.x;
    for (int i = tid; i < 768; i += 256) w2[i] = Wa2[i];
    __syncthreads();

    const int lane = tid & 31;
    const int b = blockIdx.x * 8 + (tid >> 5);
    const float* hr = h + b * 256 + lane * 8;

    float s0 = 0.f, s1 = 0.f, s2 = 0.f;
#pragma unroll
    for (int i = 0; i < 8; i++) {
        const float hv = hr[i];
        const int c = (lane * 8 + i) * 3;
        s0 += hv * w2[c]; s1 += hv * w2[c + 1]; s2 += hv * w2[c + 2];
    }
#pragma unroll
    for (int o = 16; o; o >>= 1) {
        s0 += __shfl_xor_sync(0xffffffffu, s0, o);
        s1 += __shfl_xor_sync(0xffffffffu, s1, o);
        s2 += __shfl_xor_sync(0xffffffffu, s2, o);
    }
    if (lane == 0) {
        s0 += ba2[0]; s1 += ba2[1]; s2 += ba2[2];
        const float m = fmaxf(s0, fmaxf(s1, s2));
        const float e0 = expf(s0 - m), e1 = expf(s1 - m), e2 = expf(s2 - m);
        const float inv = 1.f / (e0 + e1 + e2);
        aw[b * 3 + 0] = e0 * inv;
        aw[b * 3 + 1] = e1 * inv;
        aw[b * 3 + 2] = e2 * inv;
    }
}

// ---------------------------------------------------------------------------
// len-3 attention: one warp per (b, h).  q,k,v,ctx layout [B,3,H,K] = [3B,512].
// ---------------------------------------------------------------------------
__global__ void __launch_bounds__(256) attn_kernel(
    const float* __restrict__ q, const float* __restrict__ k,
    const float* __restrict__ v, float* __restrict__ ctx)
{
    const int wid  = (blockIdx.x * 256 + threadIdx.x) >> 5;
    const int lane = threadIdx.x & 31;
    const int b = wid >> 2, h = wid & 3;
    const int base = b * 3 * DMODEL + h * KDIM + lane * 4;

    float4 qv[3], kv[3], vv[3];
#pragma unroll
    for (int s = 0; s < 3; s++) {
        qv[s] = *reinterpret_cast<const float4*>(q + base + s * DMODEL);
        kv[s] = *reinterpret_cast<const float4*>(k + base + s * DMODEL);
        vv[s] = *reinterpret_cast<const float4*>(v + base + s * DMODEL);
    }

    const float scale = 0.08838834764831845f;   // 1/sqrt(128)
    float sc[3][3];
#pragma unroll
    for (int i = 0; i < 3; i++)
#pragma unroll
        for (int j = 0; j < 3; j++) {
            float p = qv[i].x * kv[j].x + qv[i].y * kv[j].y
                    + qv[i].z * kv[j].z + qv[i].w * kv[j].w;
#pragma unroll
            for (int o = 16; o; o >>= 1) p += __shfl_xor_sync(0xffffffffu, p, o);
            sc[i][j] = p * scale;
        }

#pragma unroll
    for (int i = 0; i < 3; i++) {
        const float m = fmaxf(sc[i][0], fmaxf(sc[i][1], sc[i][2]));
        const float e0 = expf(sc[i][0] - m), e1 = expf(sc[i][1] - m), e2 = expf(sc[i][2] - m);
        const float inv = 1.f / (e0 + e1 + e2);
        const float p0 = e0 * inv, p1 = e1 * inv, p2 = e2 * inv;
        float4 o4;
        o4.x = p0 * vv[0].x + p1 * vv[1].x + p2 * vv[2].x;
        o4.y = p0 * vv[0].y + p1 * vv[1].y + p2 * vv[2].y;
        o4.z = p0 * vv[0].z + p1 * vv[1].z + p2 * vv[2].z;
        o4.w = p0 * vv[0].w + p1 * vv[1].w + p2 * vv[2].w;
        *reinterpret_cast<float4*>(ctx + base + i * DMODEL) = o4;
    }
}

// ---------------------------------------------------------------------------
// LN1: y = LN(x + o), one warp per row of [3B, 512]
// ---------------------------------------------------------------------------
__global__ void __launch_bounds__(256) ln_add_kernel(
    const float* __restrict__ x, const float* __restrict__ o,
    const float* __restrict__ gamma, const float* __restrict__ beta,
    float* __restrict__ out)
{
    const int row  = blockIdx.x * 8 + (threadIdx.x >> 5);
    const int lane = threadIdx.x & 31;
    const float* xr = x + row * DMODEL;
    const float* orr = o + row * DMODEL;

    float4 vals[4];
    float sum = 0.f;
#pragma unroll
    for (int i = 0; i < 4; i++) {
        const int c = i * 128 + lane * 4;
        const float4 a = *reinterpret_cast<const float4*>(xr + c);
        const float4 d = *reinterpret_cast<const float4*>(orr + c);
        vals[i].x = a.x + d.x; vals[i].y = a.y + d.y;
        vals[i].z = a.z + d.z; vals[i].w = a.w + d.w;
        sum += vals[i].x + vals[i].y + vals[i].z + vals[i].w;
    }
#pragma unroll
    for (int s = 16; s; s >>= 1) sum += __shfl_xor_sync(0xffffffffu, sum, s);
    const float mean = sum * (1.f / 512.f);

    float var = 0.f;
#pragma unroll
    for (int i = 0; i < 4; i++) {
        float dx;
        dx = vals[i].x - mean; var += dx * dx;
        dx = vals[i].y - mean; var += dx * dx;
        dx = vals[i].z - mean; var += dx * dx;
        dx = vals[i].w - mean; var += dx * dx;
    }
#pragma unroll
    for (int s = 16; s; s >>= 1) var += __shfl_xor_sync(0xffffffffu, var, s);
    const float rs = rsqrtf(var * (1.f / 512.f) + 1e-6f);

#pragma unroll
    for (int i = 0; i < 4; i++) {
        const int c = i * 128 + lane * 4;
        const float4 gm = *reinterpret_cast<const float4*>(gamma + c);
        const float4 bt = *reinterpret_cast<const float4*>(beta + c);
        float4 r;
        r.x = gm.x * (vals[i].x - mean) * rs + bt.x;
        r.y = gm.y * (vals[i].y - mean) * rs + bt.y;
        r.z = gm.z * (vals[i].z - mean) * rs + bt.z;
        r.w = gm.w * (vals[i].w - mean) * rs + bt.w;
        *reinterpret_cast<float4*>(out + row * DMODEL + c) = r;
    }
}

// ---------------------------------------------------------------------------
// weighted[b,:] = sum_s aw[b,s] * y[b,s,:]
// ---------------------------------------------------------------------------
__global__ void __launch_bounds__(256) weighted_kernel(
    const float* __restrict__ y, const float* __restrict__ aw,
    float* __restrict__ w)
{
    const int idx = blockIdx.x * 256 + threadIdx.x;   // over B*128 float4s
    const int b = idx >> 7;
    const int c = (idx & 127) * 4;
    const float a0 = aw[b * 3], a1 = aw[b * 3 + 1], a2 = aw[b * 3 + 2];
    const float* yb = y + b * 1536 + c;
    const float4 y0 = *reinterpret_cast<const float4*>(yb);
    const float4 y1 = *reinterpret_cast<const float4*>(yb + 512);
    const float4 y2 = *reinterpret_cast<const float4*>(yb + 1024);
    float4 r;
    r.x = a0 * y0.x + a1 * y1.x + a2 * y2.x;
    r.y = a0 * y0.y + a1 * y1.y + a2 * y2.y;
    r.z = a0 * y0.z + a1 * y1.z + a2 * y2.z;
    r.w = a0 * y0.w + a1 * y1.w + a2 * y2.w;
    *reinterpret_cast<float4*>(w + b * 512 + c) = r;
}

// ---------------------------------------------------------------------------
// out = LN(mp + gate * weighted); mp = x[b,2,:].  One warp per row.
// ---------------------------------------------------------------------------
__global__ void __launch_bounds__(256) final_kernel(
    const float* __restrict__ x, const float* __restrict__ gate,
    const float* __restrict__ wt, const float* __restrict__ gamma,
    const float* __restrict__ beta, float* __restrict__ out)
{
    const int b    = blockIdx.x * 8 + (threadIdx.x >> 5);
    const int lane = threadIdx.x & 31;
    const float* mp = x + b * 1536 + 1024;
    const float* gr = gate + b * 512;
    const float* wr = wt + b * 512;

    float4 vals[4];
    float sum = 0.f;
#pragma unroll
    for (int i = 0; i < 4; i++) {
        const int c = i * 128 + lane * 4;
        const float4 m4 = *reinterpret_cast<const float4*>(mp + c);
        const float4 g4 = *reinterpret_cast<const float4*>(gr + c);
        const float4 w4 = *reinterpret_cast<const float4*>(wr + c);
        vals[i].x = m4.x + g4.x * w4.x;
        vals[i].y = m4.y + g4.y * w4.y;
        vals[i].z = m4.z + g4.z * w4.z;
        vals[i].w = m4.w + g4.w * w4.w;
        sum += vals[i].x + vals[i].y + vals[i].z + vals[i].w;
    }
#pragma unroll
    for (int s = 16; s; s >>= 1) sum += __shfl_xor_sync(0xffffffffu, sum, s);
    const float mean = sum * (1.f / 512.f);

    float var = 0.f;
#pragma unroll
    for (int i = 0; i < 4; i++) {
        float dx;
        dx = vals[i].x - mean; var += dx * dx;
        dx = vals[i].y - mean; var += dx * dx;
        dx = vals[i].z - mean; var += dx * dx;
        dx = vals[i].w - mean; var += dx * dx;
    }
#pragma unroll
    for (int s = 16; s; s >>= 1) var += __shfl_xor_sync(0xffffffffu, var, s);
    const float rs = rsqrtf(var * (1.f / 512.f) + 1e-6f);

#pragma unroll
    for (int i = 0; i < 4; i++) {
        const int c = i * 128 + lane * 4;
        const float4 gm = *reinterpret_cast<const float4*>(gamma + c);
        const float4 bt = *reinterpret_cast<const float4*>(beta + c);
        float4 r;
        r.x = gm.x * (vals[i].x - mean) * rs + bt.x;
        r.y = gm.y * (vals[i].y - mean) * rs + bt.y;
        r.z = gm.z * (vals[i].z - mean) * rs + bt.z;
        r.w = gm.w * (vals[i].w - mean) * rs + bt.w;
        *reinterpret_cast<float4*>(out + b * 512 + c) = r;
    }
}

// ---------------------------------------------------------------------------
// Launch
// ---------------------------------------------------------------------------
extern "C" void kernel_launch(void* const* d_in, const int* in_sizes, int n_in,
                              void* d_out, int out_size)
{
    const float* frontier = (const float*)d_in[0];
    const float* crossrb  = (const float*)d_in[1];
    const float* mapfeat  = (const float*)d_in[2];
    const float* Wf = (const float*)d_in[3];  const float* bf = (const float*)d_in[4];
    const float* Wr = (const float*)d_in[5];  const float* br = (const float*)d_in[6];
    const float* Wm = (const float*)d_in[7];  const float* bm = (const float*)d_in[8];
    const float* Wa1 = (const float*)d_in[9]; const float* ba1 = (const float*)d_in[10];
    const float* Wa2 = (const float*)d_in[11];const float* ba2 = (const float*)d_in[12];
    const float* Wq = (const float*)d_in[13]; const float* bq = (const float*)d_in[14];
    const float* Wk = (const float*)d_in[15]; const float* bk = (const float*)d_in[16];
    const float* Wv = (const float*)d_in[17]; const float* bv = (const float*)d_in[18];
    const float* Wo = (const float*)d_in[19]; const float* bo = (const float*)d_in[20];
    const float* Wg = (const float*)d_in[21]; const float* bg = (const float*)d_in[22];
    const float* gamma1 = (const float*)d_in[23]; const float* beta1 = (const float*)d_in[24];
    const float* gamma2 = (const float*)d_in[25]; const float* beta2 = (const float*)d_in[26];

    float *x, *h, *aw, *q, *k, *v, *ctx, *o, *y, *wt, *gt;
    cudaGetSymbolAddress((void**)&x,   g_x);
    cudaGetSymbolAddress((void**)&h,   g_h);
    cudaGetSymbolAddress((void**)&aw,  g_aw);
    cudaGetSymbolAddress((void**)&q,   g_q);
    cudaGetSymbolAddress((void**)&k,   g_k);
    cudaGetSymbolAddress((void**)&v,   g_v);
    cudaGetSymbolAddress((void**)&ctx, g_ctx);
    cudaGetSymbolAddress((void**)&o,   g_o);
    cudaGetSymbolAddress((void**)&y,   g_y);
    cudaGetSymbolAddress((void**)&wt,  g_wt);
    cudaGetSymbolAddress((void**)&gt,  g_gt);

    const dim3 blk(256);

    // 1) three input projections -> x[B,3,D]
    gemm_tf32<0><<<dim3(8, 128), blk>>>(frontier, 512, Wf, 512, bf, x,        1536, 512);
    gemm_tf32<0><<<dim3(8, 128), blk>>>(crossrb,  512, Wr, 512, br, x + 512,  1536, 512);
    gemm_tf32<0><<<dim3(8, 128), blk>>>(mapfeat,  512, Wm, 512, bm, x + 1024, 1536, 512);

    // 2) adaptive weights: relu(concat @ Wa1 + ba1) -> h; softmax(h @ Wa2 + ba2) -> aw
    gemm_tf32<1><<<dim3(4, 128), blk>>>(x, 1536, Wa1, 256, ba1, h, 256, 1536);
    aw_kernel<<<BATCH / 8, blk>>>(h, Wa2, ba2, aw);

    // 3) q,k,v projections over the stacked sequence [3B,512]
    gemm_tf32<0><<<dim3(8, 384), blk>>>(x, 512, Wq, 512, bq, q, 512, 512);
    gemm_tf32<0><<<dim3(8, 384), blk>>>(x, 512, Wk, 512, bk, k, 512, 512);
    gemm_tf32<0><<<dim3(8, 384), blk>>>(x, 512, Wv, 512, bv, v, 512, 512);

    // 4) len-3 attention
    attn_kernel<<<(BATCH * NHEAD) / 8, blk>>>(q, k, v, ctx);

    // 5) output projection + residual LN1
    gemm_tf32<0><<<dim3(8, 384), blk>>>(ctx, 512, Wo, 512, bo, o, 512, 512);
    ln_add_kernel<<<ROWS3 / 8, blk>>>(x, o, gamma1, beta1, y);

    // 6) adaptive combine, gate, final LN
    weighted_kernel<<<(BATCH * 128) / 256, blk>>>(y, aw, wt);
    gemm_tf32<2><<<dim3(8, 128), blk>>>(wt, 512, Wg, 512, bg, gt, 512, 512);
    final_kernel<<<BATCH / 8, blk>>>(x, gt, wt, gamma2, beta2, (float*)d_out);
}

// round 3
// speedup vs baseline: 1.0140x; 1.0140x over previous
#include <cuda_runtime.h>
#include <math.h>

// Problem constants
#define BATCH  16384
#define DMODEL 512
#define NHEAD  4
#define KDIM   128
#define ROWS3  (BATCH*3)

// ---------------------------------------------------------------------------
// Scratch (static __device__ arrays — the sanctioned no-alloc workaround)
// ---------------------------------------------------------------------------
__device__ float g_x  [ROWS3*DMODEL];   // [B,3,D]: fp,rp,mp  (also concat view [B,1536])
__device__ float g_h  [BATCH*256];      // MLP hidden
__device__ float g_aw [BATCH*3];        // adaptive softmax weights
__device__ float g_q  [ROWS3*DMODEL];
__device__ float g_k  [ROWS3*DMODEL];
__device__ float g_v  [ROWS3*DMODEL];
__device__ float g_ctx[ROWS3*DMODEL];
__device__ float g_o  [ROWS3*DMODEL];
__device__ float g_y  [ROWS3*DMODEL];   // LN1 output
__device__ float g_wt [BATCH*DMODEL];   // weighted combination
__device__ float g_gt [BATCH*DMODEL];   // sigmoid gate

// ---------------------------------------------------------------------------
// tf32 GEMM:  C[M,N] = act(A[M,K] @ W[K,N] + bias[N])
// CTA tile 128x128x32, 256 threads (8 warps as 2x4), warp tile 64x32,
// mma.sync.m16n8k8 tf32, fp32 accumulate. M%128==0, N%128==0, K%32==0.
// ---------------------------------------------------------------------------
__device__ __forceinline__ unsigned f2tf(float x) {
    unsigned u;
    asm("cvt.rna.tf32.f32 %0, %1;" : "=r"(u) : "f"(x));
    return u;
}

#define MMA_TF32(d, a, b)                                                      \
    asm volatile(                                                              \
        "mma.sync.aligned.m16n8k8.row.col.f32.tf32.tf32.f32 "                  \
        "{%0,%1,%2,%3}, {%4,%5,%6,%7}, {%8,%9}, {%0,%1,%2,%3};"                \
        : "+f"(d[0]), "+f"(d[1]), "+f"(d[2]), "+f"(d[3])                       \
        : "r"(a[0]), "r"(a[1]), "r"(a[2]), "r"(a[3]), "r"(b[0]), "r"(b[1]))

__device__ __forceinline__ void ldg_tiles(const float* __restrict__ Ab,
                                          const float* __restrict__ Wb,
                                          int lda, int ldw, int kb, int tid,
                                          float4 (&pa)[4], float4 (&pb)[4]) {
#pragma unroll
    for (int i = 0; i < 4; i++) {
        int c = tid + (i << 8);                 // 1024 float4s of A (128 rows x 8)
        pa[i] = *reinterpret_cast<const float4*>(Ab + (c >> 3) * lda + kb + ((c & 7) << 2));
    }
#pragma unroll
    for (int i = 0; i < 4; i++) {
        int c = tid + (i << 8);                 // 1024 float4s of B (32 rows x 32)
        pb[i] = *reinterpret_cast<const float4*>(Wb + (kb + (c >> 5)) * ldw + ((c & 31) << 2));
    }
}

__device__ __forceinline__ void sts_tiles(float (*As)[36], float (*Bs)[136], int tid,
                                          const float4 (&pa)[4], const float4 (&pb)[4]) {
#pragma unroll
    for (int i = 0; i < 4; i++) {
        int c = tid + (i << 8);
        float4 s = pa[i], cv;
        cv.x = __uint_as_float(f2tf(s.x));
        cv.y = __uint_as_float(f2tf(s.y));
        cv.z = __uint_as_float(f2tf(s.z));
        cv.w = __uint_as_float(f2tf(s.w));
        *reinterpret_cast<float4*>(&As[c >> 3][(c & 7) << 2]) = cv;
    }
#pragma unroll
    for (int i = 0; i < 4; i++) {
        int c = tid + (i << 8);
        float4 s = pb[i], cv;
        cv.x = __uint_as_float(f2tf(s.x));
        cv.y = __uint_as_float(f2tf(s.y));
        cv.z = __uint_as_float(f2tf(s.z));
        cv.w = __uint_as_float(f2tf(s.w));
        *reinterpret_cast<float4*>(&Bs[c >> 5][(c & 31) << 2]) = cv;
    }
}

// ACT: 0 = none, 1 = relu, 2 = sigmoid
template <int ACT>
__global__ void __launch_bounds__(256, 1) gemm_tf32(
    const float* __restrict__ A, int lda,
    const float* __restrict__ W, int ldw,
    const float* __restrict__ bias,
    float* __restrict__ C, int ldc, int K)
{
    __shared__ float As[128][36];    // [m][k], stride 36  -> 4g+t conflict-free
    __shared__ float Bs[32][136];    // [k][n], stride 136 -> 8t+g conflict-free

    const int tid  = threadIdx.x;
    const int lane = tid & 31;
    const int warp = tid >> 5;
    const int wr = warp >> 2;       // warp row 0..1 (64 rows each)
    const int wc = warp & 3;        // warp col 0..3 (32 cols each)
    const int g = lane >> 2;        // groupID
    const int t = lane & 3;         // thread-in-group
    const int m0 = blockIdx.y * 128;
    const int n0 = blockIdx.x * 128;

    const float* Ab = A + m0 * lda;
    const float* Wb = W + n0;

    float acc[4][4][4];
#pragma unroll
    for (int i = 0; i < 4; i++)
#pragma unroll
        for (int j = 0; j < 4; j++)
#pragma unroll
            for (int r = 0; r < 4; r++) acc[i][j][r] = 0.f;

    float4 pa[4], pb[4];
    ldg_tiles(Ab, Wb, lda, ldw, 0, tid, pa, pb);
    sts_tiles(As, Bs, tid, pa, pb);
    __syncthreads();

    for (int kb = 32;; kb += 32) {
        const bool more = (kb < K);
        if (more) ldg_tiles(Ab, Wb, lda, ldw, kb, tid, pa, pb);

#pragma unroll
        for (int kk = 0; kk < 4; kk++) {
            const int k8 = kk * 8;
            unsigned a[4][4], b[4][2];
#pragma unroll
            for (int mi = 0; mi < 4; mi++) {
                const int mr = wr * 64 + mi * 16 + g;
                a[mi][0] = __float_as_uint(As[mr    ][k8 + t    ]);
                a[mi][1] = __float_as_uint(As[mr + 8][k8 + t    ]);
                a[mi][2] = __float_as_uint(As[mr    ][k8 + t + 4]);
                a[mi][3] = __float_as_uint(As[mr + 8][k8 + t + 4]);
            }
#pragma unroll
            for (int ni = 0; ni < 4; ni++) {
                const int nc = wc * 32 + ni * 8 + g;
                b[ni][0] = __float_as_uint(Bs[k8 + t    ][nc]);
                b[ni][1] = __float_as_uint(Bs[k8 + t + 4][nc]);
            }
#pragma unroll
            for (int mi = 0; mi < 4; mi++)
#pragma unroll
                for (int ni = 0; ni < 4; ni++) MMA_TF32(acc[mi][ni], a[mi], b[ni]);
        }
        __syncthreads();
        if (!more) break;
        sts_tiles(As, Bs, tid, pa, pb);
        __syncthreads();
    }

    // epilogue: bias + activation, float2 stores
#pragma unroll
    for (int mi = 0; mi < 4; mi++) {
#pragma unroll
        for (int ni = 0; ni < 4; ni++) {
            const int row = m0 + wr * 64 + mi * 16 + g;
            const int col = n0 + wc * 32 + ni * 8 + 2 * t;
            const float b0 = bias[col], b1 = bias[col + 1];
            float v0 = acc[mi][ni][0] + b0;
            float v1 = acc[mi][ni][1] + b1;
            float v2 = acc[mi][ni][2] + b0;
            float v3 = acc[mi][ni][3] + b1;
            if (ACT == 1) {
                v0 = fmaxf(v0, 0.f); v1 = fmaxf(v1, 0.f);
                v2 = fmaxf(v2, 0.f); v3 = fmaxf(v3, 0.f);
            } else if (ACT == 2) {
                v0 = 1.f / (1.f + expf(-v0)); v1 = 1.f / (1.f + expf(-v1));
                v2 = 1.f / (1.f + expf(-v2)); v3 = 1.f / (1.f + expf(-v3));
            }
            *reinterpret_cast<float2*>(&C[row * ldc + col])       = make_float2(v0, v1);
            *reinterpret_cast<float2*>(&C[(row + 8) * ldc + col]) = make_float2(v2, v3);
        }
    }
}

// ---------------------------------------------------------------------------
// Adaptive weights: aw[b,:] = softmax(h[b,:] @ Wa2 + ba2).  One warp per row.
// ---------------------------------------------------------------------------
__global__ void __launch_bounds__(256) aw_kernel(
    const float* __restrict__ h, const float* __restrict__ Wa2,
    const float* __restrict__ ba2, float* __restrict__ aw)
{
    __shared__ float w2[768];
    const int tid = threadIdx.x;
    for (int i = tid; i < 768; i += 256) w2[i] = Wa2[i];
    __syncthreads();

    const int lane = tid & 31;
    const int b = blockIdx.x * 8 + (tid >> 5);
    const float* hr = h + b * 256 + lane * 8;

    float s0 = 0.f, s1 = 0.f, s2 = 0.f;
#pragma unroll
    for (int i = 0; i < 8; i++) {
        const float hv = hr[i];
        const int c = (lane * 8 + i) * 3;
        s0 += hv * w2[c]; s1 += hv * w2[c + 1]; s2 += hv * w2[c + 2];
    }
#pragma unroll
    for (int o = 16; o; o >>= 1) {
        s0 += __shfl_xor_sync(0xffffffffu, s0, o);
        s1 += __shfl_xor_sync(0xffffffffu, s1, o);
        s2 += __shfl_xor_sync(0xffffffffu, s2, o);
    }
    if (lane == 0) {
        s0 += ba2[0]; s1 += ba2[1]; s2 += ba2[2];
        const float m = fmaxf(s0, fmaxf(s1, s2));
        const float e0 = expf(s0 - m), e1 = expf(s1 - m), e2 = expf(s2 - m);
        const float inv = 1.f / (e0 + e1 + e2);
        aw[b * 3 + 0] = e0 * inv;
        aw[b * 3 + 1] = e1 * inv;
        aw[b * 3 + 2] = e2 * inv;
    }
}

// ---------------------------------------------------------------------------
// len-3 attention: one warp per (b, h).  q,k,v,ctx layout [B,3,H,K] = [3B,512].
// ---------------------------------------------------------------------------
__global__ void __launch_bounds__(256) attn_kernel(
    const float* __restrict__ q, const float* __restrict__ k,
    const float* __restrict__ v, float* __restrict__ ctx)
{
    const int wid  = (blockIdx.x * 256 + threadIdx.x) >> 5;
    const int lane = threadIdx.x & 31;
    const int b = wid >> 2, h = wid & 3;
    const int base = b * 3 * DMODEL + h * KDIM + lane * 4;

    float4 qv[3], kv[3], vv[3];
#pragma unroll
    for (int s = 0; s < 3; s++) {
        qv[s] = *reinterpret_cast<const float4*>(q + base + s * DMODEL);
        kv[s] = *reinterpret_cast<const float4*>(k + base + s * DMODEL);
        vv[s] = *reinterpret_cast<const float4*>(v + base + s * DMODEL);
    }

    const float scale = 0.08838834764831845f;   // 1/sqrt(128)
    float sc[3][3];
#pragma unroll
    for (int i = 0; i < 3; i++)
#pragma unroll
        for (int j = 0; j < 3; j++) {
            float p = qv[i].x * kv[j].x + qv[i].y * kv[j].y
                    + qv[i].z * kv[j].z + qv[i].w * kv[j].w;
#pragma unroll
            for (int o = 16; o; o >>= 1) p += __shfl_xor_sync(0xffffffffu, p, o);
            sc[i][j] = p * scale;
        }

#pragma unroll
    for (int i = 0; i < 3; i++) {
        const float m = fmaxf(sc[i][0], fmaxf(sc[i][1], sc[i][2]));
        const float e0 = expf(sc[i][0] - m), e1 = expf(sc[i][1] - m), e2 = expf(sc[i][2] - m);
        const float inv = 1.f / (e0 + e1 + e2);
        const float p0 = e0 * inv, p1 = e1 * inv, p2 = e2 * inv;
        float4 o4;
        o4.x = p0 * vv[0].x + p1 * vv[1].x + p2 * vv[2].x;
        o4.y = p0 * vv[0].y + p1 * vv[1].y + p2 * vv[2].y;
        o4.z = p0 * vv[0].z + p1 * vv[1].z + p2 * vv[2].z;
        o4.w = p0 * vv[0].w + p1 * vv[1].w + p2 * vv[2].w;
        *reinterpret_cast<float4*>(ctx + base + i * DMODEL) = o4;
    }
}

// ---------------------------------------------------------------------------
// LN1: y = LN(x + o), one warp per row of [3B, 512]
// ---------------------------------------------------------------------------
__global__ void __launch_bounds__(256) ln_add_kernel(
    const float* __restrict__ x, const float* __restrict__ o,
    const float* __restrict__ gamma, const float* __restrict__ beta,
    float* __restrict__ out)
{
    const int row  = blockIdx.x * 8 + (threadIdx.x >> 5);
    const int lane = threadIdx.x & 31;
    const float* xr = x + row * DMODEL;
    const float* orr = o + row * DMODEL;

    float4 vals[4];
    float sum = 0.f;
#pragma unroll
    for (int i = 0; i < 4; i++) {
        const int c = i * 128 + lane * 4;
        const float4 a = *reinterpret_cast<const float4*>(xr + c);
        const float4 d = *reinterpret_cast<const float4*>(orr + c);
        vals[i].x = a.x + d.x; vals[i].y = a.y + d.y;
        vals[i].z = a.z + d.z; vals[i].w = a.w + d.w;
        sum += vals[i].x + vals[i].y + vals[i].z + vals[i].w;
    }
#pragma unroll
    for (int s = 16; s; s >>= 1) sum += __shfl_xor_sync(0xffffffffu, sum, s);
    const float mean = sum * (1.f / 512.f);

    float var = 0.f;
#pragma unroll
    for (int i = 0; i < 4; i++) {
        float dx;
        dx = vals[i].x - mean; var += dx * dx;
        dx = vals[i].y - mean; var += dx * dx;
        dx = vals[i].z - mean; var += dx * dx;
        dx = vals[i].w - mean; var += dx * dx;
    }
#pragma unroll
    for (int s = 16; s; s >>= 1) var += __shfl_xor_sync(0xffffffffu, var, s);
    const float rs = rsqrtf(var * (1.f / 512.f) + 1e-6f);

#pragma unroll
    for (int i = 0; i < 4; i++) {
        const int c = i * 128 + lane * 4;
        const float4 gm = *reinterpret_cast<const float4*>(gamma + c);
        const float4 bt = *reinterpret_cast<const float4*>(beta + c);
        float4 r;
        r.x = gm.x * (vals[i].x - mean) * rs + bt.x;
        r.y = gm.y * (vals[i].y - mean) * rs + bt.y;
        r.z = gm.z * (vals[i].z - mean) * rs + bt.z;
        r.w = gm.w * (vals[i].w - mean) * rs + bt.w;
        *reinterpret_cast<float4*>(out + row * DMODEL + c) = r;
    }
}

// ---------------------------------------------------------------------------
// weighted[b,:] = sum_s aw[b,s] * y[b,s,:]
// ---------------------------------------------------------------------------
__global__ void __launch_bounds__(256) weighted_kernel(
    const float* __restrict__ y, const float* __restrict__ aw,
    float* __restrict__ w)
{
    const int idx = blockIdx.x * 256 + threadIdx.x;   // over B*128 float4s
    const int b = idx >> 7;
    const int c = (idx & 127) * 4;
    const float a0 = aw[b * 3], a1 = aw[b * 3 + 1], a2 = aw[b * 3 + 2];
    const float* yb = y + b * 1536 + c;
    const float4 y0 = *reinterpret_cast<const float4*>(yb);
    const float4 y1 = *reinterpret_cast<const float4*>(yb + 512);
    const float4 y2 = *reinterpret_cast<const float4*>(yb + 1024);
    float4 r;
    r.x = a0 * y0.x + a1 * y1.x + a2 * y2.x;
    r.y = a0 * y0.y + a1 * y1.y + a2 * y2.y;
    r.z = a0 * y0.z + a1 * y1.z + a2 * y2.z;
    r.w = a0 * y0.w + a1 * y1.w + a2 * y2.w;
    *reinterpret_cast<float4*>(w + b * 512 + c) = r;
}

// ---------------------------------------------------------------------------
// out = LN(mp + gate * weighted); mp = x[b,2,:].  One warp per row.
// ---------------------------------------------------------------------------
__global__ void __launch_bounds__(256) final_kernel(
    const float* __restrict__ x, const float* __restrict__ gate,
    const float* __restrict__ wt, const float* __restrict__ gamma,
    const float* __restrict__ beta, float* __restrict__ out)
{
    const int b    = blockIdx.x * 8 + (threadIdx.x >> 5);
    const int lane = threadIdx.x & 31;
    const float* mp = x + b * 1536 + 1024;
    const float* gr = gate + b * 512;
    const float* wr = wt + b * 512;

    float4 vals[4];
    float sum = 0.f;
#pragma unroll
    for (int i = 0; i < 4; i++) {
        const int c = i * 128 + lane * 4;
        const float4 m4 = *reinterpret_cast<const float4*>(mp + c);
        const float4 g4 = *reinterpret_cast<const float4*>(gr + c);
        const float4 w4 = *reinterpret_cast<const float4*>(wr + c);
        vals[i].x = m4.x + g4.x * w4.x;
        vals[i].y = m4.y + g4.y * w4.y;
        vals[i].z = m4.z + g4.z * w4.z;
        vals[i].w = m4.w + g4.w * w4.w;
        sum += vals[i].x + vals[i].y + vals[i].z + vals[i].w;
    }
#pragma unroll
    for (int s = 16; s; s >>= 1) sum += __shfl_xor_sync(0xffffffffu, sum, s);
    const float mean = sum * (1.f / 512.f);

    float var = 0.f;
#pragma unroll
    for (int i = 0; i < 4; i++) {
        float dx;
        dx = vals[i].x - mean; var += dx * dx;
        dx = vals[i].y - mean; var += dx * dx;
        dx = vals[i].z - mean; var += dx * dx;
        dx = vals[i].w - mean; var += dx * dx;
    }
#pragma unroll
    for (int s = 16; s; s >>= 1) var += __shfl_xor_sync(0xffffffffu, var, s);
    const float rs = rsqrtf(var * (1.f / 512.f) + 1e-6f);

#pragma unroll
    for (int i = 0; i < 4; i++) {
        const int c = i * 128 + lane * 4;
        const float4 gm = *reinterpret_cast<const float4*>(gamma + c);
        const float4 bt = *reinterpret_cast<const float4*>(beta + c);
        float4 r;
        r.x = gm.x * (vals[i].x - mean) * rs + bt.x;
        r.y = gm.y * (vals[i].y - mean) * rs + bt.y;
        r.z = gm.z * (vals[i].z - mean) * rs + bt.z;
        r.w = gm.w * (vals[i].w - mean) * rs + bt.w;
        *reinterpret_cast<float4*>(out + b * 512 + c) = r;
    }
}

// ---------------------------------------------------------------------------
// Launch
// ---------------------------------------------------------------------------
extern "C" void kernel_launch(void* const* d_in, const int* in_sizes, int n_in,
                              void* d_out, int out_size)
{
    const float* frontier = (const float*)d_in[0];
    const float* crossrb  = (const float*)d_in[1];
    const float* mapfeat  = (const float*)d_in[2];
    const float* Wf = (const float*)d_in[3];  const float* bf = (const float*)d_in[4];
    const float* Wr = (const float*)d_in[5];  const float* br = (const float*)d_in[6];
    const float* Wm = (const float*)d_in[7];  const float* bm = (const float*)d_in[8];
    const float* Wa1 = (const float*)d_in[9]; const float* ba1 = (const float*)d_in[10];
    const float* Wa2 = (const float*)d_in[11];const float* ba2 = (const float*)d_in[12];
    const float* Wq = (const float*)d_in[13]; const float* bq = (const float*)d_in[14];
    const float* Wk = (const float*)d_in[15]; const float* bk = (const float*)d_in[16];
    const float* Wv = (const float*)d_in[17]; const float* bv = (const float*)d_in[18];
    const float* Wo = (const float*)d_in[19]; const float* bo = (const float*)d_in[20];
    const float* Wg = (const float*)d_in[21]; const float* bg = (const float*)d_in[22];
    const float* gamma1 = (const float*)d_in[23]; const float* beta1 = (const float*)d_in[24];
    const float* gamma2 = (const float*)d_in[25]; const float* beta2 = (const float*)d_in[26];

    float *x, *h, *aw, *q, *k, *v, *ctx, *o, *y, *wt, *gt;
    cudaGetSymbolAddress((void**)&x,   g_x);
    cudaGetSymbolAddress((void**)&h,   g_h);
    cudaGetSymbolAddress((void**)&aw,  g_aw);
    cudaGetSymbolAddress((void**)&q,   g_q);
    cudaGetSymbolAddress((void**)&k,   g_k);
    cudaGetSymbolAddress((void**)&v,   g_v);
    cudaGetSymbolAddress((void**)&ctx, g_ctx);
    cudaGetSymbolAddress((void**)&o,   g_o);
    cudaGetSymbolAddress((void**)&y,   g_y);
    cudaGetSymbolAddress((void**)&wt,  g_wt);
    cudaGetSymbolAddress((void**)&gt,  g_gt);

    const dim3 blk(256);

    // 1) three input projections -> x[B,3,D]
    gemm_tf32<0><<<dim3(4, 128), blk>>>(frontier, 512, Wf, 512, bf, x,        1536, 512);
    gemm_tf32<0><<<dim3(4, 128), blk>>>(crossrb,  512, Wr, 512, br, x + 512,  1536, 512);
    gemm_tf32<0><<<dim3(4, 128), blk>>>(mapfeat,  512, Wm, 512, bm, x + 1024, 1536, 512);

    // 2) adaptive weights: relu(concat @ Wa1 + ba1) -> h; softmax(h @ Wa2 + ba2) -> aw
    gemm_tf32<1><<<dim3(2, 128), blk>>>(x, 1536, Wa1, 256, ba1, h, 256, 1536);
    aw_kernel<<<BATCH / 8, blk>>>(h, Wa2, ba2, aw);

    // 3) q,k,v projections over the stacked sequence [3B,512]
    gemm_tf32<0><<<dim3(4, 384), blk>>>(x, 512, Wq, 512, bq, q, 512, 512);
    gemm_tf32<0><<<dim3(4, 384), blk>>>(x, 512, Wk, 512, bk, k, 512, 512);
    gemm_tf32<0><<<dim3(4, 384), blk>>>(x, 512, Wv, 512, bv, v, 512, 512);

    // 4) len-3 attention
    attn_kernel<<<(BATCH * NHEAD) / 8, blk>>>(q, k, v, ctx);

    // 5) output projection + residual LN1
    gemm_tf32<0><<<dim3(4, 384), blk>>>(ctx, 512, Wo, 512, bo, o, 512, 512);
    ln_add_kernel<<<ROWS3 / 8, blk>>>(x, o, gamma1, beta1, y);

    // 6) adaptive combine, gate, final LN
    weighted_kernel<<<(BATCH * 128) / 256, blk>>>(y, aw, wt);
    gemm_tf32<2><<<dim3(4, 128), blk>>>(wt, 512, Wg, 512, bg, gt, 512, 512);
    final_kernel<<<BATCH / 8, blk>>>(x, gt, wt, gamma2, beta2, (float*)d_out);
}